// round 5
// baseline (speedup 1.0000x reference)
#include <cuda_runtime.h>
#include <cuda_bf16.h>

// Outputs (flat fp32, concatenated in reference tuple order):
//   [0]                      loss (scalar)
//   [1 .. B*(T-1)]           per_token_logps (B, T-1) row-major
//   [1+B*(T-1) .. +B]        avg_entropy_per_sample (B,)
//   [1+B*(T-1)+B .. +B]      avg_entropy_truncated (B,)
//
// Inputs:
//   d_in[0] logits  fp32  (B, T, V)
//   d_in[1] advantages fp32 (B,)
//   d_in[2] input_ids int32 (B, T)
//   d_in[3] labels    int32 (B, T)

#define EPS_ENT 1e-9f

// scratch for per-row entropy (B*(T-1) <= 4096 assumed)
__device__ float g_entropy[4096];

__global__ __launch_bounds__(512) void row_stats_kernel(
    const float* __restrict__ logits,
    const int* __restrict__ input_ids,
    float* __restrict__ out_logps,   // d_out + 1, length B*(T-1)
    int B, int T, int V)
{
    const int Tm1 = T - 1;
    const int r = blockIdx.x;            // row index in [0, B*Tm1)
    const int b = r / Tm1;
    const int t = r - b * Tm1;
    const size_t row_off = (size_t)(b * T + t) * (size_t)V;
    const float* row = logits + row_off;

    const int tid = threadIdx.x;
    const int nthreads = blockDim.x;

    float s = 0.0f;   // sum exp(x)
    float u = 0.0f;   // sum x * exp(x)

    const float4* row4 = (const float4*)row;
    const int n4 = V >> 2;

    #pragma unroll 8
    for (int i = tid; i < n4; i += nthreads) {
        float4 v = __ldcs(row4 + i);
        float e0 = __expf(v.x);
        float e1 = __expf(v.y);
        float e2 = __expf(v.z);
        float e3 = __expf(v.w);
        s += (e0 + e1) + (e2 + e3);
        u = fmaf(v.x, e0, u);
        u = fmaf(v.y, e1, u);
        u = fmaf(v.z, e2, u);
        u = fmaf(v.w, e3, u);
    }

    // warp reduce
    #pragma unroll
    for (int off = 16; off > 0; off >>= 1) {
        s += __shfl_xor_sync(0xFFFFFFFFu, s, off);
        u += __shfl_xor_sync(0xFFFFFFFFu, u, off);
    }

    __shared__ float ss[16], su[16];
    const int wid = tid >> 5;
    const int lid = tid & 31;
    if (lid == 0) { ss[wid] = s; su[wid] = u; }
    __syncthreads();

    if (tid == 0) {
        const int nwarps = nthreads >> 5;
        float S = 0.0f, U = 0.0f;
        for (int w = 0; w < nwarps; w++) { S += ss[w]; U += su[w]; }
        float lse = __logf(S);
        int chosen = input_ids[b * T + t + 1];
        float xl = __ldg(row + chosen);
        out_logps[r] = xl - lse;                    // TEMPERATURE = 1
        // H = lse - E_p[x] - eps*V  (first-order in eps, exact to ~1e-9 abs)
        g_entropy[r] = lse - U / S - EPS_ENT * (float)V;
    }
}

__global__ __launch_bounds__(256) void finalize_kernel(
    const float* __restrict__ advantages,
    const int* __restrict__ labels,
    float* __restrict__ d_out,
    int B, int T)
{
    const int Tm1 = T - 1;
    const int n = B * Tm1;
    __shared__ float sE[4096 > 2048 ? 2048 : 4096]; // 2048 floats
    __shared__ int   sL[2048];
    __shared__ float sMsum[64];

    const int tid = threadIdx.x;
    // cooperative stage (assumes n <= 2048; here n = 1024)
    for (int i = tid; i < n; i += blockDim.x) {
        int b = i / Tm1;
        int t = i - b * Tm1;
        sE[i] = g_entropy[i];
        sL[i] = labels[b * T + t + 1];
    }
    __syncthreads();

    if (tid < B) {
        const int b = tid;
        float sum_e = 0.0f, sum_m = 0.0f;
        float sum_et = 0.0f, sum_mt = 0.0f;
        int cum = 0;
        for (int t = 0; t < Tm1; t++) {
            int m = sL[b * Tm1 + t];
            float mf = (float)m;
            float e = sE[b * Tm1 + t];
            bool valid = (m == 1);
            cum += valid ? 1 : 0;
            bool trunc = valid && (cum >= 4) && (cum <= 100);
            sum_e += e * mf;
            sum_m += mf;
            if (trunc) { sum_et += e; sum_mt += 1.0f; }
        }
        d_out[1 + n + b]     = sum_e / sum_m;        // avg_entropy_per_sample
        d_out[1 + n + B + b] = sum_et / sum_mt;      // avg_entropy_truncated
        sMsum[b] = sum_m;
    }
    __syncthreads();

    if (tid == 0) {
        // ratio = exp(plp - stopgrad(plp)) = 1 exactly; clip(1,0.8,1.3)=1
        // per_token_loss = -min(adv, adv) = -adv[b]
        float num = 0.0f, den = 0.0f;
        for (int b = 0; b < B; b++) {
            num += -advantages[b] * sMsum[b];
            den += sMsum[b];
        }
        d_out[0] = num / den;
    }
}

extern "C" void kernel_launch(void* const* d_in, const int* in_sizes, int n_in,
                              void* d_out, int out_size)
{
    const float* logits     = (const float*)d_in[0];
    const float* advantages = (const float*)d_in[1];
    const int*   input_ids  = (const int*)d_in[2];
    const int*   labels     = (const int*)d_in[3];
    float* out = (float*)d_out;

    const int B  = in_sizes[1];               // advantages: (B,)
    const int BT = in_sizes[2];               // input_ids: (B, T)
    const int T  = BT / B;
    const int V  = (int)((long long)in_sizes[0] / (long long)BT);
    const int rows = B * (T - 1);

    row_stats_kernel<<<rows, 512>>>(logits, input_ids, out + 1, B, T, V);
    finalize_kernel<<<1, 256>>>(advantages, labels, out, B, T);
}

// round 8
// speedup vs baseline: 1.0961x; 1.0961x over previous
#include <cuda_runtime.h>
#include <cuda_bf16.h>

// Outputs (flat fp32, concatenated in reference tuple order):
//   [0]                      loss (scalar)
//   [1 .. B*(T-1)]           per_token_logps (B, T-1) row-major
//   [1+B*(T-1) .. +B]        avg_entropy_per_sample (B,)
//   [1+B*(T-1)+B .. +B]      avg_entropy_truncated (B,)
//
// Inputs:
//   d_in[0] logits  fp32  (B, T, V)
//   d_in[1] advantages fp32 (B,)
//   d_in[2] input_ids int32 (B, T)
//   d_in[3] labels    int32 (B, T)

#define EPS_ENT 1e-9f

// scratch for per-row entropy (B*(T-1) <= 4096 assumed)
__device__ float g_entropy[4096];
// monotonic ticket counter: finisher detected via (old % rows == rows-1).
// 2^32 % 1024 == 0, so phases stay aligned across graph replays / wraps.
__device__ unsigned int g_ticket;

__global__ __launch_bounds__(512) void grpo_fused_kernel(
    const float* __restrict__ logits,
    const float* __restrict__ advantages,
    const int* __restrict__ input_ids,
    const int* __restrict__ labels,
    float* __restrict__ d_out,
    int B, int T, int V)
{
    const int Tm1 = T - 1;
    const int rows = B * Tm1;
    const int r = blockIdx.x;            // row index in [0, B*Tm1)
    const int b = r / Tm1;
    const int t = r - b * Tm1;
    const size_t row_off = (size_t)(b * T + t) * (size_t)V;
    const float* row = logits + row_off;

    const int tid = threadIdx.x;
    const int nthreads = blockDim.x;

    // Hoist the dependent chosen-logit chain (input_ids -> logits[chosen],
    // ~1200 cyc of DRAM latency) so it overlaps the streaming loop.
    float xl = 0.0f;
    if (tid == 0) {
        int chosen = __ldg(input_ids + b * T + t + 1);
        xl = __ldg(row + chosen);
    }

    float s = 0.0f;   // sum exp(x)
    float u = 0.0f;   // sum x * exp(x)

    const float4* row4 = (const float4*)row;
    const int n4 = V >> 2;

    #pragma unroll 8
    for (int i = tid; i < n4; i += nthreads) {
        float4 v = __ldcs(row4 + i);
        float e0 = __expf(v.x);
        float e1 = __expf(v.y);
        float e2 = __expf(v.z);
        float e3 = __expf(v.w);
        s += (e0 + e1) + (e2 + e3);
        u = fmaf(v.x, e0, u);
        u = fmaf(v.y, e1, u);
        u = fmaf(v.z, e2, u);
        u = fmaf(v.w, e3, u);
    }

    // warp reduce
    #pragma unroll
    for (int off = 16; off > 0; off >>= 1) {
        s += __shfl_xor_sync(0xFFFFFFFFu, s, off);
        u += __shfl_xor_sync(0xFFFFFFFFu, u, off);
    }

    __shared__ float ss[16], su[16];
    __shared__ int s_is_last;
    __shared__ float sMsum[32];
    const int wid = tid >> 5;
    const int lid = tid & 31;
    if (lid == 0) { ss[wid] = s; su[wid] = u; }
    __syncthreads();

    if (tid == 0) {
        const int nwarps = nthreads >> 5;
        float S = 0.0f, U = 0.0f;
        for (int w = 0; w < nwarps; w++) { S += ss[w]; U += su[w]; }
        float lse = __logf(S);
        d_out[1 + r] = xl - lse;                    // TEMPERATURE = 1
        // H = lse - E_p[x] - eps*V  (first-order in eps, exact to ~1e-9 abs)
        g_entropy[r] = lse - U / S - EPS_ENT * (float)V;
        // Publish, then take a ticket. Last CTA runs the epilogue.
        __threadfence();
        unsigned int old = atomicAdd(&g_ticket, 1u);
        s_is_last = ((int)(old % (unsigned)rows) == rows - 1) ? 1 : 0;
    }
    __syncthreads();

    if (!s_is_last) return;

    // ---- Epilogue (last CTA only): one warp per sample ----
    const int n = rows;
    if (wid < B) {
        const int bb = wid;
        float sum_e = 0.0f, sum_m = 0.0f, sum_et = 0.0f;
        int cnt_t = 0;
        int base = 0;
        const int nchunk = (Tm1 + 31) >> 5;
        for (int c = 0; c < nchunk; c++) {
            int tt = (c << 5) + lid;
            int m = (tt < Tm1) ? __ldg(labels + bb * T + tt + 1) : 0;
            bool valid = (m == 1);
            unsigned bal = __ballot_sync(0xFFFFFFFFu, valid);
            unsigned mask_le = 0xFFFFFFFFu >> (31 - lid);
            int cum = base + __popc(bal & mask_le);     // inclusive cumsum of valid
            float e = (tt < Tm1) ? g_entropy[bb * Tm1 + tt] : 0.0f;
            float mf = (float)m;
            sum_e += e * mf;
            sum_m += mf;
            if (valid && cum >= 4 && cum <= 100) { sum_et += e; cnt_t++; }
            base += __popc(bal);
        }
        #pragma unroll
        for (int off = 16; off > 0; off >>= 1) {
            sum_e  += __shfl_xor_sync(0xFFFFFFFFu, sum_e,  off);
            sum_m  += __shfl_xor_sync(0xFFFFFFFFu, sum_m,  off);
            sum_et += __shfl_xor_sync(0xFFFFFFFFu, sum_et, off);
            cnt_t  += __shfl_xor_sync(0xFFFFFFFFu, cnt_t,  off);
        }
        if (lid == 0) {
            d_out[1 + n + bb]     = sum_e / sum_m;          // avg_entropy_per_sample
            d_out[1 + n + B + bb] = sum_et / (float)cnt_t;  // avg_entropy_truncated
            sMsum[bb] = sum_m;
        }
    }
    __syncthreads();

    if (tid == 0) {
        // ratio = exp(plp - stopgrad(plp)) = 1 exactly; clip(1,0.8,1.3)=1
        // per_token_loss = -min(adv, adv) = -adv[b]
        float num = 0.0f, den = 0.0f;
        for (int bb = 0; bb < B; bb++) {
            num += -__ldg(advantages + bb) * sMsum[bb];
            den += sMsum[bb];
        }
        d_out[0] = num / den;
    }
}

extern "C" void kernel_launch(void* const* d_in, const int* in_sizes, int n_in,
                              void* d_out, int out_size)
{
    const float* logits     = (const float*)d_in[0];
    const float* advantages = (const float*)d_in[1];
    const int*   input_ids  = (const int*)d_in[2];
    const int*   labels     = (const int*)d_in[3];
    float* out = (float*)d_out;

    const int B  = in_sizes[1];               // advantages: (B,)
    const int BT = in_sizes[2];               // input_ids: (B, T)
    const int T  = BT / B;
    const int V  = (int)((long long)in_sizes[0] / (long long)BT);
    const int rows = B * (T - 1);

    grpo_fused_kernel<<<rows, 512>>>(logits, advantages, input_ids, labels, out, B, T, V);
}